// round 1
// baseline (speedup 1.0000x reference)
#include <cuda_runtime.h>
#include <math.h>

// ---------------------------------------------------------------------------
// GatedGCN on GB300 — round 0: correct baseline
//   layer: out = sigmoid(SpMM(x@G)) * SpMM(x@W);  h = relu(out1); logits = out2
// Dims fixed by the problem: D0=256, D1=256, D2=128. N, E read from in_sizes.
// ---------------------------------------------------------------------------

#define MAXN 50000
#define D0 256
#define D1 256
#define D2 128

// Scratch (static device globals; allocation inside kernel_launch is forbidden)
__device__ float g_sg1 [(size_t)MAXN * (2 * D1)];   // [N, 512]  support|gate L1
__device__ float g_agg1[(size_t)MAXN * (2 * D1)];   // [N, 512]  aggregated L1
__device__ float g_h   [(size_t)MAXN * D1];         // [N, 256]  relu-gated hidden
__device__ float g_sg2 [(size_t)MAXN * (2 * D2)];   // [N, 256]  support|gate L2
__device__ float g_agg2[(size_t)MAXN * (2 * D2)];   // [N, 256]  aggregated L2

// ---------------------------------------------------------------------------
// Tiled fp32 GEMM computing C[M, 2*Nw] = A[M,K] @ [Bw | Bg]  (Bw,Bg: [K,Nw])
// 64x64 tile, K-tile 32, 256 threads, 4x4 per thread.
// ---------------------------------------------------------------------------
#define TM 64
#define TN 64
#define TK 32

__global__ __launch_bounds__(256)
void gemm_dual(const float* __restrict__ A,
               const float* __restrict__ Bw,
               const float* __restrict__ Bg,
               float* __restrict__ C,
               int M, int K, int Nw)
{
    __shared__ float As[TK][TM];        // transposed A tile
    __shared__ float Bs[TK][TN];

    const int tid = threadIdx.x;
    const int tx  = tid & 15;           // 0..15  -> 4 output cols each
    const int ty  = tid >> 4;           // 0..15  -> 4 output rows each

    const int nbase = blockIdx.x * TN;  // global output column base
    const int m0    = blockIdx.y * TM;

    // choose W or G half (TN divides Nw for all our shapes)
    const float* __restrict__ B = (nbase < Nw) ? Bw : Bg;
    const int ncol0 = nbase % Nw;
    const int ldC   = 2 * Nw;

    float acc[4][4];
#pragma unroll
    for (int i = 0; i < 4; i++)
#pragma unroll
        for (int j = 0; j < 4; j++) acc[i][j] = 0.f;

    for (int k0 = 0; k0 < K; k0 += TK) {
        // --- load A tile: 64 rows x 32 k = 512 float4, 2 per thread ---
#pragma unroll
        for (int it = 0; it < 2; it++) {
            int idx   = tid + it * 256;
            int arow  = idx >> 3;          // /8 float4 per row
            int acol4 = idx & 7;
            int grow  = m0 + arow;
            float4 v = make_float4(0.f, 0.f, 0.f, 0.f);
            if (grow < M)
                v = *reinterpret_cast<const float4*>(&A[(size_t)grow * K + k0 + acol4 * 4]);
            As[acol4 * 4 + 0][arow] = v.x;
            As[acol4 * 4 + 1][arow] = v.y;
            As[acol4 * 4 + 2][arow] = v.z;
            As[acol4 * 4 + 3][arow] = v.w;
        }
        // --- load B tile: 32 k x 64 cols = 512 float4, 2 per thread ---
#pragma unroll
        for (int it = 0; it < 2; it++) {
            int idx   = tid + it * 256;
            int brow  = idx >> 4;          // /16 float4 per row
            int bcol4 = idx & 15;
            float4 v = *reinterpret_cast<const float4*>(
                &B[(size_t)(k0 + brow) * Nw + ncol0 + bcol4 * 4]);
            *reinterpret_cast<float4*>(&Bs[brow][bcol4 * 4]) = v;
        }
        __syncthreads();

#pragma unroll
        for (int kk = 0; kk < TK; kk++) {
            float4 a = *reinterpret_cast<const float4*>(&As[kk][ty * 4]);
            float4 b = *reinterpret_cast<const float4*>(&Bs[kk][tx * 4]);
            float ar[4] = {a.x, a.y, a.z, a.w};
            float br[4] = {b.x, b.y, b.z, b.w};
#pragma unroll
            for (int i = 0; i < 4; i++)
#pragma unroll
                for (int j = 0; j < 4; j++)
                    acc[i][j] = fmaf(ar[i], br[j], acc[i][j]);
        }
        __syncthreads();
    }

    // --- store ---
#pragma unroll
    for (int i = 0; i < 4; i++) {
        int grow = m0 + ty * 4 + i;
        if (grow < M) {
            float4 v = make_float4(acc[i][0], acc[i][1], acc[i][2], acc[i][3]);
            *reinterpret_cast<float4*>(&C[(size_t)grow * ldC + nbase + tx * 4]) = v;
        }
    }
}

// ---------------------------------------------------------------------------
// SpMM scatter: for each edge e, dst[rows[e], :] += vals[e] * src[cols[e], :]
// One warp per edge; vectorized red.global.add.v4.f32 scatters.
// D is 512 (layer1 fused) or 256 (layer2 fused).
// ---------------------------------------------------------------------------
__device__ __forceinline__ void red_add_v4(float4* addr, float4 v)
{
    asm volatile("red.global.add.v4.f32 [%0], {%1, %2, %3, %4};"
                 :: "l"(addr), "f"(v.x), "f"(v.y), "f"(v.z), "f"(v.w)
                 : "memory");
}

__global__ __launch_bounds__(256)
void spmm_scatter(const int* __restrict__ rows,
                  const int* __restrict__ cols,
                  const float* __restrict__ vals,
                  const float* __restrict__ src,
                  float* __restrict__ dst,
                  int E, int D)
{
    const int warp = (blockIdx.x * blockDim.x + threadIdx.x) >> 5;
    const int lane = threadIdx.x & 31;
    if (warp >= E) return;

    const int   r = rows[warp];
    const int   c = cols[warp];
    const float v = vals[warp];

    const float4* __restrict__ s = reinterpret_cast<const float4*>(src + (size_t)c * D);
    float4* __restrict__       d = reinterpret_cast<float4*>(dst + (size_t)r * D);

    const int n4 = D >> 2;
    for (int i = lane; i < n4; i += 32) {
        float4 t = s[i];
        t.x *= v; t.y *= v; t.z *= v; t.w *= v;
        red_add_v4(&d[i], t);
    }
}

// ---------------------------------------------------------------------------
// Elementwise: h = relu(sigmoid(gate) * support)      (layer 1)
//              out = sigmoid(gate) * support          (layer 2)
// ---------------------------------------------------------------------------
__device__ __forceinline__ float sigmoidf_(float x)
{
    return 1.0f / (1.0f + expf(-x));
}

__global__ __launch_bounds__(256)
void gate_relu_l1(const float* __restrict__ agg, float* __restrict__ h, int total)
{
    int idx = blockIdx.x * blockDim.x + threadIdx.x;
    if (idx >= total) return;            // total = N*256
    int row = idx >> 8;
    int col = idx & 255;
    float sup = agg[(size_t)row * 512 + col];
    float gat = agg[(size_t)row * 512 + 256 + col];
    float y = sigmoidf_(gat) * sup;
    h[idx] = y > 0.f ? y : 0.f;
}

__global__ __launch_bounds__(256)
void gate_l2(const float* __restrict__ agg, float* __restrict__ out, int total)
{
    int idx = blockIdx.x * blockDim.x + threadIdx.x;
    if (idx >= total) return;            // total = N*128
    int row = idx >> 7;
    int col = idx & 127;
    float sup = agg[(size_t)row * 256 + col];
    float gat = agg[(size_t)row * 256 + 128 + col];
    out[idx] = sigmoidf_(gat) * sup;
}

// ---------------------------------------------------------------------------
// kernel_launch
// Inputs (metadata order): x, rows, cols, vals, W1, G1, W2, G2
// ---------------------------------------------------------------------------
extern "C" void kernel_launch(void* const* d_in, const int* in_sizes, int n_in,
                              void* d_out, int out_size)
{
    const float* x    = (const float*)d_in[0];
    const int*   rows = (const int*)  d_in[1];
    const int*   cols = (const int*)  d_in[2];
    const float* vals = (const float*)d_in[3];
    const float* W1   = (const float*)d_in[4];
    const float* G1   = (const float*)d_in[5];
    const float* W2   = (const float*)d_in[6];
    const float* G2   = (const float*)d_in[7];
    float* out = (float*)d_out;

    const int N = in_sizes[0] / D0;
    const int E = in_sizes[1];

    float *sg1, *agg1, *h, *sg2, *agg2;
    cudaGetSymbolAddress((void**)&sg1,  g_sg1);
    cudaGetSymbolAddress((void**)&agg1, g_agg1);
    cudaGetSymbolAddress((void**)&h,    g_h);
    cudaGetSymbolAddress((void**)&sg2,  g_sg2);
    cudaGetSymbolAddress((void**)&agg2, g_agg2);

    const int mtiles = (N + TM - 1) / TM;
    const int spmm_blocks = (E + 7) / 8;        // 8 warps (edges) per block

    // zero aggregation buffers (memset nodes are graph-capturable)
    cudaMemsetAsync(agg1, 0, (size_t)N * (2 * D1) * sizeof(float));
    cudaMemsetAsync(agg2, 0, (size_t)N * (2 * D2) * sizeof(float));

    // ---- layer 1 ----
    gemm_dual<<<dim3((2 * D1) / TN, mtiles), 256>>>(x, W1, G1, sg1, N, D0, D1);
    spmm_scatter<<<spmm_blocks, 256>>>(rows, cols, vals, sg1, agg1, E, 2 * D1);
    {
        int total = N * D1;
        gate_relu_l1<<<(total + 255) / 256, 256>>>(agg1, h, total);
    }

    // ---- layer 2 ----
    gemm_dual<<<dim3((2 * D2) / TN, mtiles), 256>>>(h, W2, G2, sg2, N, D1, D2);
    spmm_scatter<<<spmm_blocks, 256>>>(rows, cols, vals, sg2, agg2, E, 2 * D2);
    {
        int total = N * D2;
        gate_l2<<<(total + 255) / 256, 256>>>(agg2, out, total);
    }
}

// round 2
// speedup vs baseline: 1.8975x; 1.8975x over previous
#include <cuda_runtime.h>
#include <math.h>

// ---------------------------------------------------------------------------
// GatedGCN on GB300 — round 1
//   - CSR built on-device per launch (histogram + scan + scatter)
//   - gather-based SpMM, fused sigmoid-gate (+relu) epilogue, no atomics on
//     feature data, no agg buffers, no memset of 150 MB
//   - SIMT fp32 GEMM upgraded to 128x128x16 tile, 8x8 per thread
// ---------------------------------------------------------------------------

#define MAXN 50000
#define MAXE 800000
#define D0 256
#define D1 256
#define D2 128

// Scratch (device globals; no allocation allowed in kernel_launch)
__device__ float g_sg1 [(size_t)MAXN * (2 * D1)];   // [N, 512]  support|gate L1
__device__ float g_h   [(size_t)MAXN * D1];         // [N, 256]  hidden
__device__ float g_sg2 [(size_t)MAXN * (2 * D2)];   // [N, 256]  support|gate L2
__device__ int   g_counts[MAXN];
__device__ int   g_rowptr[MAXN + 1];
__device__ int   g_cursor[MAXN];
__device__ int   g_ecol[MAXE];
__device__ float g_eval[MAXE];

// ---------------------------------------------------------------------------
// CSR build
// ---------------------------------------------------------------------------
__global__ void hist_kernel(const int* __restrict__ rows, int* __restrict__ counts, int E)
{
    int i = blockIdx.x * blockDim.x + threadIdx.x;
    if (i < E) atomicAdd(&counts[rows[i]], 1);
}

// single-block scan over n counts -> exclusive rowptr (+ copy to cursor)
__global__ __launch_bounds__(1024)
void scan_kernel(const int* __restrict__ counts, int* __restrict__ rowptr,
                 int* __restrict__ cursor, int n)
{
    __shared__ int warpsums[32];
    __shared__ int s_running;
    const int tid  = threadIdx.x;
    const int lane = tid & 31;
    const int wid  = tid >> 5;
    if (tid == 0) s_running = 0;
    __syncthreads();

    for (int base = 0; base < n; base += 1024) {
        int i = base + tid;
        int v = (i < n) ? counts[i] : 0;
        int x = v;
#pragma unroll
        for (int d = 1; d < 32; d <<= 1) {
            int y = __shfl_up_sync(0xffffffffu, x, d);
            if (lane >= d) x += y;
        }
        if (lane == 31) warpsums[wid] = x;
        __syncthreads();
        if (wid == 0) {
            int w = warpsums[lane];
#pragma unroll
            for (int d = 1; d < 32; d <<= 1) {
                int y = __shfl_up_sync(0xffffffffu, w, d);
                if (lane >= d) w += y;
            }
            warpsums[lane] = w;
        }
        __syncthreads();
        int warpoff = (wid > 0) ? warpsums[wid - 1] : 0;
        int excl    = x - v + warpoff;
        int run     = s_running;
        if (i < n) { rowptr[i] = run + excl; cursor[i] = run + excl; }
        __syncthreads();
        if (tid == 1023) s_running = run + warpsums[31];
        __syncthreads();
    }
    if (threadIdx.x == 0) rowptr[n] = s_running;
}

__global__ void scatter_kernel(const int* __restrict__ rows, const int* __restrict__ cols,
                               const float* __restrict__ vals, int* __restrict__ cursor,
                               int* __restrict__ ecol, float* __restrict__ eval_, int E)
{
    int i = blockIdx.x * blockDim.x + threadIdx.x;
    if (i < E) {
        int pos = atomicAdd(&cursor[rows[i]], 1);
        ecol[pos]  = cols[i];
        eval_[pos] = vals[i];
    }
}

// ---------------------------------------------------------------------------
// GEMM: C[M, 2*Nw] = A[M,K] @ [Bw | Bg],  128x128x16 tiles, 8x8 per thread
// ---------------------------------------------------------------------------
#define BM 128
#define BN 128
#define BK 16
#define APAD 4   // As row pad (floats) to cut store bank conflicts

__global__ __launch_bounds__(256)
void gemm_dual(const float* __restrict__ A,
               const float* __restrict__ Bw,
               const float* __restrict__ Bg,
               float* __restrict__ C,
               int M, int K, int Nw)
{
    __shared__ float As[BK][BM + APAD];   // transposed A tile
    __shared__ float Bs[BK][BN];

    const int tid = threadIdx.x;
    const int tx  = tid & 15;             // 8 output cols each
    const int ty  = tid >> 4;             // 8 output rows each

    const int nbase = blockIdx.x * BN;
    const int m0    = blockIdx.y * BM;

    const float* __restrict__ B = (nbase < Nw) ? Bw : Bg;
    const int ncol0 = nbase % Nw;
    const int ldC   = 2 * Nw;

    float acc[8][8];
#pragma unroll
    for (int i = 0; i < 8; i++)
#pragma unroll
        for (int j = 0; j < 8; j++) acc[i][j] = 0.f;

    for (int k0 = 0; k0 < K; k0 += BK) {
        // A tile: 128 rows x 16 k = 512 float4 (2/thread), stored transposed
#pragma unroll
        for (int it = 0; it < 2; it++) {
            int idx   = tid + it * 256;
            int arow  = idx >> 2;           // 4 float4 per row
            int acol4 = idx & 3;
            int grow  = m0 + arow;
            float4 v = make_float4(0.f, 0.f, 0.f, 0.f);
            if (grow < M)
                v = *reinterpret_cast<const float4*>(&A[(size_t)grow * K + k0 + acol4 * 4]);
            As[acol4 * 4 + 0][arow] = v.x;
            As[acol4 * 4 + 1][arow] = v.y;
            As[acol4 * 4 + 2][arow] = v.z;
            As[acol4 * 4 + 3][arow] = v.w;
        }
        // B tile: 16 k x 128 cols = 512 float4 (2/thread)
#pragma unroll
        for (int it = 0; it < 2; it++) {
            int idx   = tid + it * 256;
            int brow  = idx >> 5;           // 32 float4 per row
            int bcol4 = idx & 31;
            *reinterpret_cast<float4*>(&Bs[brow][bcol4 * 4]) =
                *reinterpret_cast<const float4*>(
                    &B[(size_t)(k0 + brow) * Nw + ncol0 + bcol4 * 4]);
        }
        __syncthreads();

#pragma unroll
        for (int kk = 0; kk < BK; kk++) {
            float4 a0 = *reinterpret_cast<const float4*>(&As[kk][ty * 8]);
            float4 a1 = *reinterpret_cast<const float4*>(&As[kk][ty * 8 + 4]);
            float4 b0 = *reinterpret_cast<const float4*>(&Bs[kk][tx * 8]);
            float4 b1 = *reinterpret_cast<const float4*>(&Bs[kk][tx * 8 + 4]);
            float ar[8] = {a0.x, a0.y, a0.z, a0.w, a1.x, a1.y, a1.z, a1.w};
            float br[8] = {b0.x, b0.y, b0.z, b0.w, b1.x, b1.y, b1.z, b1.w};
#pragma unroll
            for (int i = 0; i < 8; i++)
#pragma unroll
                for (int j = 0; j < 8; j++)
                    acc[i][j] = fmaf(ar[i], br[j], acc[i][j]);
        }
        __syncthreads();
    }

#pragma unroll
    for (int i = 0; i < 8; i++) {
        int grow = m0 + ty * 8 + i;
        if (grow < M) {
            float* cp = &C[(size_t)grow * ldC + nbase + tx * 8];
            *reinterpret_cast<float4*>(cp)     = make_float4(acc[i][0], acc[i][1], acc[i][2], acc[i][3]);
            *reinterpret_cast<float4*>(cp + 4) = make_float4(acc[i][4], acc[i][5], acc[i][6], acc[i][7]);
        }
    }
}

// ---------------------------------------------------------------------------
// Gather SpMM with fused gating.
// src: [N, D] = [support | gate], out: [N, D/2] = sigmoid(agg_gate)*agg_support
// One block per row; NT = D/4 threads, each owns one float4 of features.
// ---------------------------------------------------------------------------
__device__ __forceinline__ float sigmoidf_(float x) { return 1.0f / (1.0f + __expf(-x)); }

template <int D, bool RELU>
__global__ void spmm_gate(const int* __restrict__ rowptr,
                          const int* __restrict__ ecol,
                          const float* __restrict__ eval_,
                          const float* __restrict__ src,
                          float* __restrict__ out)
{
    constexpr int NT   = D / 4;
    constexpr int HALF = NT / 2;
    __shared__ float sgate[D / 2];

    const int r = blockIdx.x;
    const int t = threadIdx.x;
    const int s = rowptr[r];
    const int e = rowptr[r + 1];

    const float4* __restrict__ srcv = reinterpret_cast<const float4*>(src);

    float4 acc = make_float4(0.f, 0.f, 0.f, 0.f);

    int i = s;
    for (; i + 1 < e; i += 2) {
        int   c0 = ecol[i];     int   c1 = ecol[i + 1];
        float v0 = eval_[i];    float v1 = eval_[i + 1];
        float4 g0 = srcv[(size_t)c0 * NT + t];
        float4 g1 = srcv[(size_t)c1 * NT + t];
        acc.x = fmaf(v0, g0.x, acc.x); acc.y = fmaf(v0, g0.y, acc.y);
        acc.z = fmaf(v0, g0.z, acc.z); acc.w = fmaf(v0, g0.w, acc.w);
        acc.x = fmaf(v1, g1.x, acc.x); acc.y = fmaf(v1, g1.y, acc.y);
        acc.z = fmaf(v1, g1.z, acc.z); acc.w = fmaf(v1, g1.w, acc.w);
    }
    if (i < e) {
        int   c = ecol[i];
        float v = eval_[i];
        float4 g = srcv[(size_t)c * NT + t];
        acc.x = fmaf(v, g.x, acc.x); acc.y = fmaf(v, g.y, acc.y);
        acc.z = fmaf(v, g.z, acc.z); acc.w = fmaf(v, g.w, acc.w);
    }

    if (t >= HALF) {
        int o = (t - HALF) * 4;
        sgate[o + 0] = sigmoidf_(acc.x);
        sgate[o + 1] = sigmoidf_(acc.y);
        sgate[o + 2] = sigmoidf_(acc.z);
        sgate[o + 3] = sigmoidf_(acc.w);
    }
    __syncthreads();
    if (t < HALF) {
        float4 sg = *reinterpret_cast<const float4*>(&sgate[t * 4]);
        float4 o;
        o.x = acc.x * sg.x; o.y = acc.y * sg.y;
        o.z = acc.z * sg.z; o.w = acc.w * sg.w;
        if (RELU) {
            o.x = fmaxf(o.x, 0.f); o.y = fmaxf(o.y, 0.f);
            o.z = fmaxf(o.z, 0.f); o.w = fmaxf(o.w, 0.f);
        }
        *reinterpret_cast<float4*>(&out[(size_t)r * (D / 2) + t * 4]) = o;
    }
}

// ---------------------------------------------------------------------------
// kernel_launch — inputs: x, rows, cols, vals, W1, G1, W2, G2
// ---------------------------------------------------------------------------
extern "C" void kernel_launch(void* const* d_in, const int* in_sizes, int n_in,
                              void* d_out, int out_size)
{
    const float* x    = (const float*)d_in[0];
    const int*   rows = (const int*)  d_in[1];
    const int*   cols = (const int*)  d_in[2];
    const float* vals = (const float*)d_in[3];
    const float* W1   = (const float*)d_in[4];
    const float* G1   = (const float*)d_in[5];
    const float* W2   = (const float*)d_in[6];
    const float* G2   = (const float*)d_in[7];
    float* out = (float*)d_out;

    const int N = in_sizes[0] / D0;
    const int E = in_sizes[1];

    float *sg1, *h, *sg2, *evalp;
    int *counts, *rowptr, *cursor, *ecol;
    cudaGetSymbolAddress((void**)&sg1,    g_sg1);
    cudaGetSymbolAddress((void**)&h,      g_h);
    cudaGetSymbolAddress((void**)&sg2,    g_sg2);
    cudaGetSymbolAddress((void**)&counts, g_counts);
    cudaGetSymbolAddress((void**)&rowptr, g_rowptr);
    cudaGetSymbolAddress((void**)&cursor, g_cursor);
    cudaGetSymbolAddress((void**)&ecol,   g_ecol);
    cudaGetSymbolAddress((void**)&evalp,  g_eval);

    const int mtiles = (N + BM - 1) / BM;
    const int eblocks = (E + 255) / 256;

    // ---- build CSR ----
    cudaMemsetAsync(counts, 0, (size_t)N * sizeof(int));
    hist_kernel<<<eblocks, 256>>>(rows, counts, E);
    scan_kernel<<<1, 1024>>>(counts, rowptr, cursor, N);
    scatter_kernel<<<eblocks, 256>>>(rows, cols, vals, cursor, ecol, evalp, E);

    // ---- layer 1 ----
    gemm_dual<<<dim3((2 * D1) / BN, mtiles), 256>>>(x, W1, G1, sg1, N, D0, D1);
    spmm_gate<2 * D1, true><<<N, (2 * D1) / 4>>>(rowptr, ecol, evalp, sg1, h);

    // ---- layer 2 ----
    gemm_dual<<<dim3((2 * D2) / BN, mtiles), 256>>>(h, W2, G2, sg2, N, D1, D2);
    spmm_gate<2 * D2, false><<<N, (2 * D2) / 4>>>(rowptr, ecol, evalp, sg2, out);
}

// round 4
// speedup vs baseline: 3.1658x; 1.6683x over previous
#include <cuda_runtime.h>
#include <cuda_bf16.h>
#include <math.h>
#include <stdint.h>

// ---------------------------------------------------------------------------
// GatedGCN on GB300 — round 3
//   GEMMs on tensor cores via portable mma.sync bf16 (sm_103 PTX-legal;
//   tcgen05 PTX requires .target sm_103a which this harness cannot emit).
//   Split-precision 3-term bf16: C = Ah*Bh + Ah*Bl + Al*Bh, virtual K=768.
//   SpMM: CSR gather with fused gate (+relu); layer-1 epilogue writes the
//   bf16 hi/lo split consumed by the layer-2 GEMM.
// ---------------------------------------------------------------------------

#define MAXN 50000
#define MAXE 800000
#define D0 256
#define D1 256
#define D2 128

// ---------------- scratch (device globals) ----------------
__device__ __nv_bfloat16 g_A2x[(size_t)MAXN * 512];   // [N,512] = [xh | xl]
__device__ __nv_bfloat16 g_A2h[(size_t)MAXN * 512];   // [N,512] = [hh | hl]
__device__ __nv_bfloat16 g_Bt1[(size_t)512 * 768];    // [2*256][768] stacked W1|G1
__device__ __nv_bfloat16 g_Bt2[(size_t)256 * 768];    // [2*128][768] stacked W2|G2
__device__ float g_sg1[(size_t)MAXN * 512];           // support|gate layer1 (fp32)
__device__ float g_sg2[(size_t)MAXN * 256];           // support|gate layer2 (fp32)
__device__ int   g_counts[MAXN];
__device__ int   g_rowptr[MAXN + 1];
__device__ int   g_cursor[MAXN];
__device__ int   g_ecol[MAXE];
__device__ float g_eval[MAXE];

// ---------------- PTX helpers ----------------
__device__ __forceinline__ uint32_t smem_u32(const void* p) {
    uint32_t a;
    asm("{ .reg .u64 t; cvta.to.shared.u64 t, %1; cvt.u32.u64 %0, t; }" : "=r"(a) : "l"(p));
    return a;
}
__device__ __forceinline__ uint32_t swz(uint32_t o) { return o ^ ((o >> 3) & 0x70); }

__device__ __forceinline__ void cp16(uint32_t dst, const void* src, int sz) {
    asm volatile("cp.async.cg.shared.global [%0], [%1], 16, %2;"
                 :: "r"(dst), "l"(src), "r"(sz));
}
__device__ __forceinline__ void cp_commit() { asm volatile("cp.async.commit_group;"); }
__device__ __forceinline__ void cp_wait1()  { asm volatile("cp.async.wait_group 1;"); }

__device__ __forceinline__ void ldm_x4(uint32_t& r0, uint32_t& r1, uint32_t& r2, uint32_t& r3,
                                       uint32_t addr) {
    asm volatile("ldmatrix.sync.aligned.m8n8.x4.shared.b16 {%0,%1,%2,%3}, [%4];"
                 : "=r"(r0), "=r"(r1), "=r"(r2), "=r"(r3) : "r"(addr));
}
__device__ __forceinline__ void mma_bf16(float& d0, float& d1, float& d2, float& d3,
                                         uint32_t a0, uint32_t a1, uint32_t a2, uint32_t a3,
                                         uint32_t b0, uint32_t b1) {
    asm volatile("mma.sync.aligned.m16n8k16.row.col.f32.bf16.bf16.f32 "
                 "{%0,%1,%2,%3}, {%4,%5,%6,%7}, {%8,%9}, {%0,%1,%2,%3};"
                 : "+f"(d0), "+f"(d1), "+f"(d2), "+f"(d3)
                 : "r"(a0), "r"(a1), "r"(a2), "r"(a3), "r"(b0), "r"(b1));
}

// ---------------------------------------------------------------------------
// bf16 hi/lo split helpers
// ---------------------------------------------------------------------------
__device__ __forceinline__ void split_bf16(float v, __nv_bfloat16& h, __nv_bfloat16& l) {
    h = __float2bfloat16(v);
    l = __float2bfloat16(v - __bfloat162float(h));
}

// x [N,256] fp32 -> A2 [N,512] bf16 = [hi | lo]
__global__ void conv_x(const float* __restrict__ x, __nv_bfloat16* __restrict__ a2, int N)
{
    int idx = blockIdx.x * blockDim.x + threadIdx.x;   // one per 4 elems
    if (idx >= N * 64) return;
    int r  = idx >> 6;
    int c4 = (idx & 63) * 4;
    float4 v = *reinterpret_cast<const float4*>(&x[(size_t)r * 256 + c4]);
    float vv[4] = {v.x, v.y, v.z, v.w};
    __nv_bfloat16 h[4], l[4];
#pragma unroll
    for (int j = 0; j < 4; j++) split_bf16(vv[j], h[j], l[j]);
    __nv_bfloat16* base = a2 + (size_t)r * 512 + c4;
    *reinterpret_cast<__nv_bfloat162*>(base)           = __halves2bfloat162(h[0], h[1]);
    *reinterpret_cast<__nv_bfloat162*>(base + 2)       = __halves2bfloat162(h[2], h[3]);
    *reinterpret_cast<__nv_bfloat162*>(base + 256)     = __halves2bfloat162(l[0], l[1]);
    *reinterpret_cast<__nv_bfloat162*>(base + 256 + 2) = __halves2bfloat162(l[2], l[3]);
}

// W,G [256,Nw] fp32 -> Bt [2Nw][768] bf16, K stacked [Bh; Bl; Bh]
__global__ void conv_w(const float* __restrict__ W, const float* __restrict__ G,
                       __nv_bfloat16* __restrict__ Bt, int Nw)
{
    int idx = blockIdx.x * blockDim.x + threadIdx.x;
    int twoNw = 2 * Nw;
    if (idx >= twoNw * 256) return;
    int n = idx % twoNw;
    int k = idx / twoNw;
    float w = (n < Nw) ? W[(size_t)k * Nw + n] : G[(size_t)k * Nw + (n - Nw)];
    __nv_bfloat16 h, l;
    split_bf16(w, h, l);
    __nv_bfloat16* row = Bt + (size_t)n * 768;
    row[k]       = h;
    row[256 + k] = l;
    row[512 + k] = h;
}

// ---------------------------------------------------------------------------
// CSR build
// ---------------------------------------------------------------------------
__global__ void hist_kernel(const int* __restrict__ rows, int* __restrict__ counts, int E)
{
    int i = blockIdx.x * blockDim.x + threadIdx.x;
    if (i < E) atomicAdd(&counts[rows[i]], 1);
}

__global__ __launch_bounds__(1024)
void scan_kernel(const int* __restrict__ counts, int* __restrict__ rowptr,
                 int* __restrict__ cursor, int n)
{
    __shared__ int warpsums[32];
    __shared__ int s_running;
    const int tid  = threadIdx.x;
    const int lane = tid & 31;
    const int wid  = tid >> 5;
    if (tid == 0) s_running = 0;
    __syncthreads();

    for (int base = 0; base < n; base += 1024) {
        int i = base + tid;
        int v = (i < n) ? counts[i] : 0;
        int x = v;
#pragma unroll
        for (int d = 1; d < 32; d <<= 1) {
            int y = __shfl_up_sync(0xffffffffu, x, d);
            if (lane >= d) x += y;
        }
        if (lane == 31) warpsums[wid] = x;
        __syncthreads();
        if (wid == 0) {
            int w = warpsums[lane];
#pragma unroll
            for (int d = 1; d < 32; d <<= 1) {
                int y = __shfl_up_sync(0xffffffffu, w, d);
                if (lane >= d) w += y;
            }
            warpsums[lane] = w;
        }
        __syncthreads();
        int warpoff = (wid > 0) ? warpsums[wid - 1] : 0;
        int excl    = x - v + warpoff;
        int run     = s_running;
        if (i < n) { rowptr[i] = run + excl; cursor[i] = run + excl; }
        __syncthreads();
        if (tid == 1023) s_running = run + warpsums[31];
        __syncthreads();
    }
    if (threadIdx.x == 0) rowptr[n] = s_running;
}

__global__ void scatter_kernel(const int* __restrict__ rows, const int* __restrict__ cols,
                               const float* __restrict__ vals, int* __restrict__ cursor,
                               int* __restrict__ ecol, float* __restrict__ eval_, int E)
{
    int i = blockIdx.x * blockDim.x + threadIdx.x;
    if (i < E) {
        int pos = atomicAdd(&cursor[rows[i]], 1);
        ecol[pos]  = cols[i];
        eval_[pos] = vals[i];
    }
}

// ---------------------------------------------------------------------------
// mma.sync GEMM: C[M, 2Nw] fp32 = A2[M,512]bf16 (x) Bt[2Nw,768]bf16 (K=768)
// 128x128 CTA tile, BK=64 chunks (12), double-buffered cp.async, SW128 layout.
// 8 warps in 4x2 grid; warp tile 32(m) x 64(n); m16n8k16 HMMA.
// ---------------------------------------------------------------------------
#define CH_BYTES 16384                    // 128 rows x 128 bytes (one stage A or B)
#define SM_A0 0
#define SM_B0 (2 * CH_BYTES)
#define SM_TOTAL (4 * CH_BYTES)           // 65536
#define NCHUNK 12

__global__ __launch_bounds__(256)
void gemm_mma(const __nv_bfloat16* __restrict__ A2,   // [M, 512]
              const __nv_bfloat16* __restrict__ Bt,   // [2Nw, 768]
              float* __restrict__ C,                  // [M, ldC]
              int M, int ldC)
{
    extern __shared__ char smem[];
    const uint32_t sb = smem_u32(smem);
    const int tid  = threadIdx.x;
    const int wid  = tid >> 5;
    const int lane = tid & 31;
    const int wm   = wid & 3;             // 0..3 -> m offset 32*wm
    const int wn   = wid >> 2;            // 0..1 -> n offset 64*wn
    const int m0    = blockIdx.y * 128;
    const int nbase = blockIdx.x * 128;

    const char* Ab = (const char*)A2;
    const char* Bb = (const char*)Bt;

    auto load_chunk = [&](int kc, int st) {
        const uint32_t sA = sb + SM_A0 + st * CH_BYTES;
        const uint32_t sB = sb + SM_B0 + st * CH_BYTES;
        const int ak = (kc < 4) ? kc : kc - 4;      // A chunk: Ah,Ah,Al over segs
        const size_t abyte = (size_t)ak * 128;      // 64 bf16 = 128 B
        const size_t bbyte = (size_t)kc * 128;
#pragma unroll
        for (int i = 0; i < 4; i++) {
            int g   = tid + i * 256;                // 0..1023
            int row = g >> 3;                       // 0..127
            int c   = (g & 7) * 16;                 // 0..112 step 16
            int m   = m0 + row;
            int sz  = (m < M) ? 16 : 0;
            int mc  = (m < M) ? m : (M - 1);
            cp16(sA + swz((uint32_t)(row * 128 + c)),
                 Ab + (size_t)mc * 1024 + abyte + c, sz);
            cp16(sB + swz((uint32_t)(row * 128 + c)),
                 Bb + (size_t)(nbase + row) * 1536 + bbyte + c, 16);
        }
        cp_commit();
    };

    float acc[2][8][4];
#pragma unroll
    for (int i = 0; i < 2; i++)
#pragma unroll
        for (int j = 0; j < 8; j++)
#pragma unroll
            for (int q = 0; q < 4; q++) acc[i][j][q] = 0.f;

    load_chunk(0, 0);
    load_chunk(1, 1);

    // ldmatrix lane-address components (constant across chunks)
    const int a_row_in_tile = lane & 15;            // 0..15
    const int a_chunk_half  = lane >> 4;            // 0/1 -> k+0 / k+8
    const int b_row_in_pair = lane & 7;             // 0..7
    const int b_chunk_half  = (lane >> 3) & 1;      // k half
    const int b_tile_sel    = lane >> 4;            // which n8 of the pair

    for (int kc = 0; kc < NCHUNK; kc++) {
        const int st = kc & 1;
        const uint32_t sA = sb + SM_A0 + st * CH_BYTES;
        const uint32_t sB = sb + SM_B0 + st * CH_BYTES;

        cp_wait1();
        __syncthreads();

#pragma unroll
        for (int ks = 0; ks < 4; ks++) {            // 4 x k16 per chunk
            // A fragments: 2 m-tiles of 16
            uint32_t a[2][4];
#pragma unroll
            for (int i = 0; i < 2; i++) {
                int row = wm * 32 + i * 16 + a_row_in_tile;
                uint32_t addr = sA + swz((uint32_t)(row * 128 + (ks * 2 + a_chunk_half) * 16));
                ldm_x4(a[i][0], a[i][1], a[i][2], a[i][3], addr);
            }
            // B fragments: 8 n8-tiles, loaded 2 at a time
            uint32_t b[8][2];
#pragma unroll
            for (int jp = 0; jp < 4; jp++) {
                int row = wn * 64 + (jp * 2 + b_tile_sel) * 8 + b_row_in_pair;
                uint32_t addr = sB + swz((uint32_t)(row * 128 + (ks * 2 + b_chunk_half) * 16));
                uint32_t r0, r1, r2, r3;
                ldm_x4(r0, r1, r2, r3, addr);
                b[jp * 2 + 0][0] = r0; b[jp * 2 + 0][1] = r1;
                b[jp * 2 + 1][0] = r2; b[jp * 2 + 1][1] = r3;
            }
#pragma unroll
            for (int i = 0; i < 2; i++)
#pragma unroll
                for (int j = 0; j < 8; j++)
                    mma_bf16(acc[i][j][0], acc[i][j][1], acc[i][j][2], acc[i][j][3],
                             a[i][0], a[i][1], a[i][2], a[i][3],
                             b[j][0], b[j][1]);
        }

        __syncthreads();
        if (kc + 2 < NCHUNK) load_chunk(kc + 2, st);
        else cp_commit();                            // keep group numbering
    }

    // ---- epilogue: write fp32 C ----
    const int qrow = lane >> 2;                      // 0..7
    const int qcol = (lane & 3) * 2;
#pragma unroll
    for (int i = 0; i < 2; i++) {
        int mA = m0 + wm * 32 + i * 16 + qrow;
        int mB = mA + 8;
#pragma unroll
        for (int j = 0; j < 8; j++) {
            int col = nbase + wn * 64 + j * 8 + qcol;
            if (mA < M)
                *reinterpret_cast<float2*>(&C[(size_t)mA * ldC + col]) =
                    make_float2(acc[i][j][0], acc[i][j][1]);
            if (mB < M)
                *reinterpret_cast<float2*>(&C[(size_t)mB * ldC + col]) =
                    make_float2(acc[i][j][2], acc[i][j][3]);
        }
    }
}

// ---------------------------------------------------------------------------
// Gather SpMM with fused gating.
// src: [N, D] = [support | gate]; out = sigmoid(agg_gate) * agg_support.
// SPLIT: writes bf16 hi/lo pair (feeds next tensor GEMM); else fp32.
// ---------------------------------------------------------------------------
__device__ __forceinline__ float sigmoidf_(float x) { return 1.0f / (1.0f + __expf(-x)); }

template <int D, bool RELU, bool SPLIT>
__global__ void spmm_gate(const int* __restrict__ rowptr,
                          const int* __restrict__ ecol,
                          const float* __restrict__ eval_,
                          const float* __restrict__ src,
                          void* __restrict__ outv)
{
    constexpr int NT   = D / 4;
    constexpr int HALF = NT / 2;
    constexpr int DH   = D / 2;
    __shared__ float sgate[DH];

    const int r = blockIdx.x;
    const int t = threadIdx.x;
    const int s = rowptr[r];
    const int e = rowptr[r + 1];

    const float4* __restrict__ srcv = reinterpret_cast<const float4*>(src);

    float4 acc = make_float4(0.f, 0.f, 0.f, 0.f);

    int i = s;
    for (; i + 1 < e; i += 2) {
        int   c0 = ecol[i];     int   c1 = ecol[i + 1];
        float v0 = eval_[i];    float v1 = eval_[i + 1];
        float4 g0 = srcv[(size_t)c0 * NT + t];
        float4 g1 = srcv[(size_t)c1 * NT + t];
        acc.x = fmaf(v0, g0.x, acc.x); acc.y = fmaf(v0, g0.y, acc.y);
        acc.z = fmaf(v0, g0.z, acc.z); acc.w = fmaf(v0, g0.w, acc.w);
        acc.x = fmaf(v1, g1.x, acc.x); acc.y = fmaf(v1, g1.y, acc.y);
        acc.z = fmaf(v1, g1.z, acc.z); acc.w = fmaf(v1, g1.w, acc.w);
    }
    if (i < e) {
        int   c = ecol[i];
        float v = eval_[i];
        float4 g = srcv[(size_t)c * NT + t];
        acc.x = fmaf(v, g.x, acc.x); acc.y = fmaf(v, g.y, acc.y);
        acc.z = fmaf(v, g.z, acc.z); acc.w = fmaf(v, g.w, acc.w);
    }

    if (t >= HALF) {
        int o = (t - HALF) * 4;
        sgate[o + 0] = sigmoidf_(acc.x);
        sgate[o + 1] = sigmoidf_(acc.y);
        sgate[o + 2] = sigmoidf_(acc.z);
        sgate[o + 3] = sigmoidf_(acc.w);
    }
    __syncthreads();
    if (t < HALF) {
        float4 sg = *reinterpret_cast<const float4*>(&sgate[t * 4]);
        float o[4];
        o[0] = acc.x * sg.x; o[1] = acc.y * sg.y;
        o[2] = acc.z * sg.z; o[3] = acc.w * sg.w;
        if (RELU) {
#pragma unroll
            for (int j = 0; j < 4; j++) o[j] = fmaxf(o[j], 0.f);
        }
        if (SPLIT) {
            __nv_bfloat16 h[4], l[4];
#pragma unroll
            for (int j = 0; j < 4; j++) split_bf16(o[j], h[j], l[j]);
            __nv_bfloat16* base = (__nv_bfloat16*)outv + (size_t)r * (2 * DH) + t * 4;
            *reinterpret_cast<__nv_bfloat162*>(base)          = __halves2bfloat162(h[0], h[1]);
            *reinterpret_cast<__nv_bfloat162*>(base + 2)      = __halves2bfloat162(h[2], h[3]);
            *reinterpret_cast<__nv_bfloat162*>(base + DH)     = __halves2bfloat162(l[0], l[1]);
            *reinterpret_cast<__nv_bfloat162*>(base + DH + 2) = __halves2bfloat162(l[2], l[3]);
        } else {
            *reinterpret_cast<float4*>((float*)outv + (size_t)r * DH + t * 4) =
                make_float4(o[0], o[1], o[2], o[3]);
        }
    }
}

// ---------------------------------------------------------------------------
// kernel_launch — inputs: x, rows, cols, vals, W1, G1, W2, G2
// ---------------------------------------------------------------------------
extern "C" void kernel_launch(void* const* d_in, const int* in_sizes, int n_in,
                              void* d_out, int out_size)
{
    const float* x    = (const float*)d_in[0];
    const int*   rows = (const int*)  d_in[1];
    const int*   cols = (const int*)  d_in[2];
    const float* vals = (const float*)d_in[3];
    const float* W1   = (const float*)d_in[4];
    const float* G1   = (const float*)d_in[5];
    const float* W2   = (const float*)d_in[6];
    const float* G2   = (const float*)d_in[7];
    float* out = (float*)d_out;

    const int N = in_sizes[0] / D0;
    const int E = in_sizes[1];

    __nv_bfloat16 *A2x, *A2h, *Bt1, *Bt2;
    float *sg1, *sg2, *evalp;
    int *counts, *rowptr, *cursor, *ecol;
    cudaGetSymbolAddress((void**)&A2x,    g_A2x);
    cudaGetSymbolAddress((void**)&A2h,    g_A2h);
    cudaGetSymbolAddress((void**)&Bt1,    g_Bt1);
    cudaGetSymbolAddress((void**)&Bt2,    g_Bt2);
    cudaGetSymbolAddress((void**)&sg1,    g_sg1);
    cudaGetSymbolAddress((void**)&sg2,    g_sg2);
    cudaGetSymbolAddress((void**)&counts, g_counts);
    cudaGetSymbolAddress((void**)&rowptr, g_rowptr);
    cudaGetSymbolAddress((void**)&cursor, g_cursor);
    cudaGetSymbolAddress((void**)&ecol,   g_ecol);
    cudaGetSymbolAddress((void**)&evalp,  g_eval);

    cudaFuncSetAttribute(gemm_mma, cudaFuncAttributeMaxDynamicSharedMemorySize, SM_TOTAL);

    const int mtiles  = (N + 127) / 128;
    const int eblocks = (E + 255) / 256;

    // ---- operand prep ----
    conv_x<<<(N * 64 + 255) / 256, 256>>>(x, A2x, N);
    conv_w<<<(2 * D1 * 256 + 255) / 256, 256>>>(W1, G1, Bt1, D1);
    conv_w<<<(2 * D2 * 256 + 255) / 256, 256>>>(W2, G2, Bt2, D2);

    // ---- build CSR ----
    cudaMemsetAsync(counts, 0, (size_t)N * sizeof(int));
    hist_kernel<<<eblocks, 256>>>(rows, counts, E);
    scan_kernel<<<1, 1024>>>(counts, rowptr, cursor, N);
    scatter_kernel<<<eblocks, 256>>>(rows, cols, vals, cursor, ecol, evalp, E);

    // ---- layer 1 ----
    gemm_mma<<<dim3(4, mtiles), 256, SM_TOTAL>>>(A2x, Bt1, sg1, N, 512);
    spmm_gate<512, true, true><<<N, 128>>>(rowptr, ecol, evalp, sg1, A2h);

    // ---- layer 2 ----
    gemm_mma<<<dim3(2, mtiles), 256, SM_TOTAL>>>(A2h, Bt2, sg2, N, 256);
    spmm_gate<256, false, false><<<N, 64>>>(rowptr, ecol, evalp, sg2, out);
}